// round 11
// baseline (speedup 1.0000x reference)
#include <cuda_runtime.h>
#include <cstdint>

#define Bc 8
#define Cc 64
#define Nc 4096
#define Kc 20
#define NS 21       // keep top-21 (self + 20), self dropped after merge
#define PARTS 4
#define PLEN (Nc / PARTS)   // 1024 candidates per part

typedef unsigned long long u64;

// ---------------- device scratch (no allocations allowed) ----------------
__device__ float  g_sq[Bc * Nc];                  // squared norms per point
__device__ u64    g_part[Bc * Nc * PARTS * NS];   // per-part sorted top-21 keys
__device__ int    g_idx[Bc * Nc * Kc];            // knn indices (within batch)
__device__ float  g_P[Bc * Nc * 64];              // (W1-W2)·x_n + b   [b][n][o]
__device__ float  g_Q[Bc * Nc * 64];              // W2·x_m            [b][m][o]
__device__ double g_sum[64];
__device__ double g_sumsq[64];
__device__ float  g_scale[64];
__device__ float  g_shift[64];

// ---------------- kernel 0: zero BN accumulators (graph-replay safe) -----
__global__ void k_zero() {
    int o = threadIdx.x;
    if (o < 64) { g_sum[o] = 0.0; g_sumsq[o] = 0.0; }
}

// ---------------- kernel 1: squared norms --------------------------------
__global__ void k_sqnorm(const float* __restrict__ x) {
    int i = blockIdx.x * blockDim.x + threadIdx.x;   // i = b*N + n
    if (i >= Bc * Nc) return;
    int b = i / Nc, n = i % Nc;
    const float* xb = x + (size_t)b * Cc * Nc + n;
    float s = 0.f;
#pragma unroll
    for (int c = 0; c < Cc; ++c) {
        float v = xb[(size_t)c * Nc];
        s = fmaf(v, v, s);
    }
    g_sq[i] = s;
}

// ---------------- kNN helpers --------------------------------------------
// Monotone map float -> u32 so integer compare == (float, then idx) lexicographic.
__device__ __forceinline__ u64 make_key(float d, int m) {
    int bb = __float_as_int(d);
    unsigned ub = (unsigned)bb ^ ((unsigned)(bb >> 31) | 0x80000000u);
    return ((u64)ub << 32) | (unsigned)m;
}

// Branchless shift-insert into sorted-ascending e[0..20].
// Precondition: cand < e[20].
__device__ __forceinline__ void insert21(u64 (&e)[NS], u64 cand) {
    bool ltc = true;              // cand < conceptual e[21]
#pragma unroll
    for (int s = NS - 1; s >= 1; --s) {
        bool ltp = cand < e[s - 1];
        e[s] = ltp ? e[s - 1] : (ltc ? cand : e[s]);
        ltc = ltp;
    }
    e[0] = ltc ? cand : e[0];
}

#define FMA2(acc, a, b) asm("fma.rn.f32x2 %0, %1, %2, %0;" : "+l"(acc) : "l"(a), "l"(b))

// ---------------- kernel 2: partial kNN ----------------------------------
// Each block: 128 queries (thread per query), one of PARTS candidate
// quarters (1024 candidates). Query in registers; candidate tiles of 32 in
// SMEM; packed f32x2 FMAs. Emits a sorted top-21 key list per (query, part).
__global__ __launch_bounds__(128) void k_knn_part(const float* __restrict__ x) {
    __shared__ float cs[Cc][32];
    __shared__ float csq[32];

    const int t    = threadIdx.x;
    const int part = blockIdx.y;
    const int b    = blockIdx.z;
    const int n0   = blockIdx.x * 128;
    const float* xb = x + (size_t)b * Cc * Nc;

    // query into registers
    float q[Cc];
#pragma unroll
    for (int c = 0; c < Cc; ++c)
        q[c] = xb[(size_t)c * Nc + n0 + t];
    const float sqq = g_sq[b * Nc + n0 + t];

    // sorted top-21 keys, ascending; sentinel inits above any real key
    u64 e[NS];
#pragma unroll
    for (int s = 0; s < NS; ++s) e[s] = 0xFFFFFFFF00000000ull + (unsigned)s;

    const int mbase = part * PLEN;
    for (int m0 = mbase; m0 < mbase + PLEN; m0 += 32) {
        __syncthreads();
        // cooperative coalesced load of 32x64 candidate tile
        for (int idx = t; idx < 32 * Cc; idx += 128) {
            int c = idx >> 5, m = idx & 31;
            cs[c][m] = xb[(size_t)c * Nc + m0 + m];
        }
        if (t < 32) csq[t] = g_sq[b * Nc + m0 + t];
        __syncthreads();

        for (int j = 0; j < 32; j += 8) {
            u64 a01 = 0ull, a23 = 0ull, a45 = 0ull, a67 = 0ull;
#pragma unroll
            for (int c = 0; c < Cc; ++c) {
                u64 qq;
                asm("mov.b64 %0, {%1, %1};" : "=l"(qq) : "f"(q[c]));
                ulonglong2 p0 = *reinterpret_cast<const ulonglong2*>(&cs[c][j]);
                ulonglong2 p1 = *reinterpret_cast<const ulonglong2*>(&cs[c][j + 4]);
                FMA2(a01, qq, p0.x);
                FMA2(a23, qq, p0.y);
                FMA2(a45, qq, p1.x);
                FMA2(a67, qq, p1.y);
            }
            float d[8];
            asm("mov.b64 {%0, %1}, %2;" : "=f"(d[0]), "=f"(d[1]) : "l"(a01));
            asm("mov.b64 {%0, %1}, %2;" : "=f"(d[2]), "=f"(d[3]) : "l"(a23));
            asm("mov.b64 {%0, %1}, %2;" : "=f"(d[4]), "=f"(d[5]) : "l"(a45));
            asm("mov.b64 {%0, %1}, %2;" : "=f"(d[6]), "=f"(d[7]) : "l"(a67));

            u64 k[8];
#pragma unroll
            for (int i = 0; i < 8; ++i) {
                float dd = sqq + csq[(m0 - mbase + j + i) & 31] - 2.f * d[i];
                k[i] = make_key(dd, m0 + j + i);
            }
            // gate the group with one branch
            u64 kmin = k[0];
#pragma unroll
            for (int i = 1; i < 8; ++i) kmin = (k[i] < kmin) ? k[i] : kmin;
            if (kmin < e[NS - 1]) {
#pragma unroll
                for (int i = 0; i < 8; ++i)
                    if (k[i] < e[NS - 1]) insert21(e, k[i]);
            }
        }
    }

    // write sorted part list
    size_t base = ((size_t)(b * Nc + n0 + t) * PARTS + part) * NS;
#pragma unroll
    for (int s = 0; s < NS; ++s) g_part[base + s] = e[s];
}

// ---------------- kernel 2b: merge part lists -----------------------------
__global__ __launch_bounds__(256) void k_merge() {
    int i = blockIdx.x * 256 + threadIdx.x;   // query id = b*N + n
    if (i >= Bc * Nc) return;
    size_t base = (size_t)i * PARTS * NS;

    u64 e[NS];
#pragma unroll
    for (int s = 0; s < NS; ++s) e[s] = g_part[base + s];

    for (int p = 1; p < PARTS; ++p) {
        const u64* pl = &g_part[base + (size_t)p * NS];
#pragma unroll 1
        for (int s = 0; s < NS; ++s) {
            u64 cand = pl[s];
            if (cand >= e[NS - 1]) break;   // part lists are sorted ascending
            insert21(e, cand);
        }
    }

    // e[0] is the self/nearest (dropped, mirrors idx[:,:,1:]); order of the
    // remaining 20 is irrelevant downstream (sum / max over k).
    int ob = i * Kc;
#pragma unroll
    for (int s = 1; s < NS; ++s)
        g_idx[ob + s - 1] = (int)(e[s] & 0xFFFFFFFFu);
}

// ---------------- kernel 3: P,Q = small GEMMs -----------------------------
// P[b][n][o] = sum_c (W[o][c]-W[o][64+c]) x[b][c][n] + bias[o]
// Q[b][n][o] = sum_c  W[o][64+c]          x[b][c][n]
__global__ __launch_bounds__(256) void k_pq(const float* __restrict__ x,
                                            const float* __restrict__ W,
                                            const float* __restrict__ bias) {
    __shared__ float Wp[Cc][64];
    __shared__ float Wq[Cc][64];
    const int tid = threadIdx.x;
    for (int i = tid; i < 64 * Cc; i += 256) {
        int o = i >> 6, c = i & 63;
        float w1 = W[o * 2 * Cc + c];
        float w2 = W[o * 2 * Cc + Cc + c];
        Wp[c][o] = w1 - w2;
        Wq[c][o] = w2;
    }
    __syncthreads();

    const int o  = tid & 63, nl = tid >> 6;
    const int b  = blockIdx.y;
    const int n0 = blockIdx.x * 64;
    const float bv = bias[o];

    for (int ni = 0; ni < 8; ++ni) {
        int n = n0 + ni * 8 + nl;            // + twin column n+4
        const float* xp = x + (size_t)b * Cc * Nc + n;
        float p0 = 0.f, q0 = 0.f, p1 = 0.f, q1 = 0.f;
#pragma unroll
        for (int c = 0; c < Cc; ++c) {
            float xv0 = __ldg(&xp[(size_t)c * Nc]);
            float xv1 = __ldg(&xp[(size_t)c * Nc + 4]);
            float wp = Wp[c][o], wq = Wq[c][o];
            p0 = fmaf(wp, xv0, p0);
            q0 = fmaf(wq, xv0, q0);
            p1 = fmaf(wp, xv1, p1);
            q1 = fmaf(wq, xv1, q1);
        }
        size_t r0 = ((size_t)(b * Nc + n)) * 64 + o;
        g_P[r0] = p0 + bv;          g_Q[r0] = q0;
        g_P[r0 + 4 * 64] = p1 + bv; g_Q[r0 + 4 * 64] = q1;
    }
}

// ---------------- kernel 4: BN statistics pass ----------------------------
__global__ __launch_bounds__(256) void k_stats() {
    const int tid = threadIdx.x;
    const int o = tid & 63, nl = tid >> 6;
    const int b = blockIdx.y;
    const int n0 = blockIdx.x * 32;

    float s = 0.f, ss = 0.f;
    for (int ni = 0; ni < 8; ++ni) {
        int n = n0 + ni * 4 + nl;
        int row = b * Nc + n;
        float pv = g_P[(size_t)row * 64 + o];
        const int* ip = &g_idx[row * Kc];
#pragma unroll
        for (int k = 0; k < Kc; ++k) {
            int m = ip[k];
            float qv = g_Q[((size_t)(b * Nc + m)) * 64 + o];
            float y = pv + qv;
            s += y;
            ss = fmaf(y, y, ss);
        }
    }
    __shared__ float rs[4][64], rss[4][64];
    rs[nl][o] = s; rss[nl][o] = ss;
    __syncthreads();
    if (nl == 0) {
        float st  = rs[0][o] + rs[1][o] + rs[2][o] + rs[3][o];
        float sst = rss[0][o] + rss[1][o] + rss[2][o] + rss[3][o];
        atomicAdd(&g_sum[o],   (double)st);
        atomicAdd(&g_sumsq[o], (double)sst);
    }
}

// ---------------- kernel 5: finalize BN coefficients ----------------------
__global__ void k_finalize(const float* __restrict__ gamma,
                           const float* __restrict__ beta) {
    int o = threadIdx.x;
    if (o < 64) {
        const double cnt = (double)Bc * Nc * Kc;
        double mean = g_sum[o] / cnt;
        double var  = g_sumsq[o] / cnt - mean * mean;
        float sc = gamma[o] * (float)(1.0 / sqrt(var + 1e-5));
        g_scale[o] = sc;
        g_shift[o] = beta[o] - (float)mean * sc;
    }
}

// ---------------- kernel 6: normalize + relu + max over k -----------------
__global__ __launch_bounds__(256) void k_out(float* __restrict__ out) {
    __shared__ float tile[64][33];   // +1 pad: conflict-free transpose
    const int tid = threadIdx.x;
    const int o = tid & 63, nl = tid >> 6;
    const int b = blockIdx.y;
    const int n0 = blockIdx.x * 32;
    const float sc = g_scale[o], sh = g_shift[o];

    for (int ni = 0; ni < 8; ++ni) {
        int n = n0 + ni * 4 + nl;
        int row = b * Nc + n;
        float pv = g_P[(size_t)row * 64 + o];
        const int* ip = &g_idx[row * Kc];
        float best = -3.4e38f;
#pragma unroll
        for (int k = 0; k < Kc; ++k) {
            int m = ip[k];
            float qv = g_Q[((size_t)(b * Nc + m)) * 64 + o];
            float v = fmaf(pv + qv, sc, sh);
            best = fmaxf(best, v);
        }
        // max_k relu(v) == relu(max_k v)
        tile[o][ni * 4 + nl] = fmaxf(best, 0.f);
    }
    __syncthreads();

    // coalesced store: out layout (B, O, N)
    const int lane = tid & 31, w = tid >> 5;   // 8 warps
    for (int o2 = w; o2 < 64; o2 += 8) {
        out[((size_t)(b * 64 + o2)) * Nc + n0 + lane] = tile[o2][lane];
    }
}

// ---------------- launcher -------------------------------------------------
extern "C" void kernel_launch(void* const* d_in, const int* in_sizes, int n_in,
                              void* d_out, int out_size) {
    const float* x     = (const float*)d_in[0];   // (B, C, N)
    const float* W     = (const float*)d_in[1];   // (O, 2C)
    const float* bias  = (const float*)d_in[2];   // (O,)
    const float* gamma = (const float*)d_in[3];   // (O,)
    const float* beta  = (const float*)d_in[4];   // (O,)
    float* out = (float*)d_out;                   // (B, O, N)

    k_zero<<<1, 64>>>();
    k_sqnorm<<<(Bc * Nc + 255) / 256, 256>>>(x);
    k_knn_part<<<dim3(Nc / 128, PARTS, Bc), 128>>>(x);
    k_merge<<<(Bc * Nc + 255) / 256, 256>>>();
    k_pq<<<dim3(Nc / 64, Bc), 256>>>(x, W, bias);
    k_stats<<<dim3(Nc / 32, Bc), 256>>>();
    k_finalize<<<1, 64>>>(gamma, beta);
    k_out<<<dim3(Nc / 32, Bc), 256>>>(out);
}

// round 12
// speedup vs baseline: 1.0006x; 1.0006x over previous
#include <cuda_runtime.h>
#include <cstdint>

#define Bc 8
#define Cc 64
#define Nc 4096
#define Kc 20
#define NS 21       // keep top-21 (self + 20), self dropped after merge
#define PARTS 4
#define PLEN (Nc / PARTS)   // 1024 candidates per part

typedef unsigned long long u64;

// ---------------- device scratch (no allocations allowed) ----------------
__device__ float  g_sq[Bc * Nc];                  // squared norms per point
__device__ u64    g_part[Bc * Nc * PARTS * NS];   // per-part sorted top-21 keys
__device__ int    g_idx[Bc * Nc * Kc];            // knn indices (within batch)
__device__ float  g_P[Bc * Nc * 64];              // (W1-W2)·x_n + b   [b][n][o]
__device__ float  g_Q[Bc * Nc * 64];              // W2·x_m            [b][m][o]
__device__ double g_sum[64];
__device__ double g_sumsq[64];
__device__ float  g_scale[64];
__device__ float  g_shift[64];

// ---------------- kernel 0: zero BN accumulators (graph-replay safe) -----
__global__ void k_zero() {
    int o = threadIdx.x;
    if (o < 64) { g_sum[o] = 0.0; g_sumsq[o] = 0.0; }
}

// ---------------- kernel 1: squared norms --------------------------------
__global__ void k_sqnorm(const float* __restrict__ x) {
    int i = blockIdx.x * blockDim.x + threadIdx.x;   // i = b*N + n
    if (i >= Bc * Nc) return;
    int b = i / Nc, n = i % Nc;
    const float* xb = x + (size_t)b * Cc * Nc + n;
    float s = 0.f;
#pragma unroll
    for (int c = 0; c < Cc; ++c) {
        float v = xb[(size_t)c * Nc];
        s = fmaf(v, v, s);
    }
    g_sq[i] = s;
}

// ---------------- kNN helpers --------------------------------------------
// Monotone map float -> u32 so integer compare == (float, then idx) lexicographic.
__device__ __forceinline__ u64 make_key(float d, int m) {
    int bb = __float_as_int(d);
    unsigned ub = (unsigned)bb ^ ((unsigned)(bb >> 31) | 0x80000000u);
    return ((u64)ub << 32) | (unsigned)m;
}

// Branchless shift-insert into sorted-ascending e[0..20].
// Precondition: cand < e[20].
__device__ __forceinline__ void insert21(u64 (&e)[NS], u64 cand) {
    bool ltc = true;              // cand < conceptual e[21]
#pragma unroll
    for (int s = NS - 1; s >= 1; --s) {
        bool ltp = cand < e[s - 1];
        e[s] = ltp ? e[s - 1] : (ltc ? cand : e[s]);
        ltc = ltp;
    }
    e[0] = ltc ? cand : e[0];
}

#define FMA2(acc, a, b) asm("fma.rn.f32x2 %0, %1, %2, %0;" : "+l"(acc) : "l"(a), "l"(b))

// ---------------- kernel 2: partial kNN ----------------------------------
// Each block: 128 queries (thread per query), one of PARTS candidate
// quarters (1024 candidates). Query in registers; candidate tiles of 32 in
// SMEM; packed f32x2 FMAs. Emits a sorted top-21 key list per (query, part).
__global__ __launch_bounds__(128) void k_knn_part(const float* __restrict__ x) {
    __shared__ float cs[Cc][32];
    __shared__ float csq[32];

    const int t    = threadIdx.x;
    const int part = blockIdx.y;
    const int b    = blockIdx.z;
    const int n0   = blockIdx.x * 128;
    const float* xb = x + (size_t)b * Cc * Nc;

    // query into registers
    float q[Cc];
#pragma unroll
    for (int c = 0; c < Cc; ++c)
        q[c] = xb[(size_t)c * Nc + n0 + t];
    const float sqq = g_sq[b * Nc + n0 + t];

    // sorted top-21 keys, ascending; sentinel inits above any real key
    u64 e[NS];
#pragma unroll
    for (int s = 0; s < NS; ++s) e[s] = 0xFFFFFFFF00000000ull + (unsigned)s;

    const int mbase = part * PLEN;
    for (int m0 = mbase; m0 < mbase + PLEN; m0 += 32) {
        __syncthreads();
        // cooperative coalesced load of 32x64 candidate tile
        for (int idx = t; idx < 32 * Cc; idx += 128) {
            int c = idx >> 5, m = idx & 31;
            cs[c][m] = xb[(size_t)c * Nc + m0 + m];
        }
        if (t < 32) csq[t] = g_sq[b * Nc + m0 + t];
        __syncthreads();

        for (int j = 0; j < 32; j += 8) {
            u64 a01 = 0ull, a23 = 0ull, a45 = 0ull, a67 = 0ull;
#pragma unroll
            for (int c = 0; c < Cc; ++c) {
                u64 qq;
                asm("mov.b64 %0, {%1, %1};" : "=l"(qq) : "f"(q[c]));
                ulonglong2 p0 = *reinterpret_cast<const ulonglong2*>(&cs[c][j]);
                ulonglong2 p1 = *reinterpret_cast<const ulonglong2*>(&cs[c][j + 4]);
                FMA2(a01, qq, p0.x);
                FMA2(a23, qq, p0.y);
                FMA2(a45, qq, p1.x);
                FMA2(a67, qq, p1.y);
            }
            float d[8];
            asm("mov.b64 {%0, %1}, %2;" : "=f"(d[0]), "=f"(d[1]) : "l"(a01));
            asm("mov.b64 {%0, %1}, %2;" : "=f"(d[2]), "=f"(d[3]) : "l"(a23));
            asm("mov.b64 {%0, %1}, %2;" : "=f"(d[4]), "=f"(d[5]) : "l"(a45));
            asm("mov.b64 {%0, %1}, %2;" : "=f"(d[6]), "=f"(d[7]) : "l"(a67));

            u64 k[8];
#pragma unroll
            for (int i = 0; i < 8; ++i) {
                float dd = sqq + csq[(m0 - mbase + j + i) & 31] - 2.f * d[i];
                k[i] = make_key(dd, m0 + j + i);
            }
            // gate the group with one branch
            u64 kmin = k[0];
#pragma unroll
            for (int i = 1; i < 8; ++i) kmin = (k[i] < kmin) ? k[i] : kmin;
            if (kmin < e[NS - 1]) {
#pragma unroll
                for (int i = 0; i < 8; ++i)
                    if (k[i] < e[NS - 1]) insert21(e, k[i]);
            }
        }
    }

    // write sorted part list
    size_t base = ((size_t)(b * Nc + n0 + t) * PARTS + part) * NS;
#pragma unroll
    for (int s = 0; s < NS; ++s) g_part[base + s] = e[s];
}

// ---------------- kernel 2b: merge part lists -----------------------------
__global__ __launch_bounds__(256) void k_merge() {
    int i = blockIdx.x * 256 + threadIdx.x;   // query id = b*N + n
    if (i >= Bc * Nc) return;
    size_t base = (size_t)i * PARTS * NS;

    u64 e[NS];
#pragma unroll
    for (int s = 0; s < NS; ++s) e[s] = g_part[base + s];

    for (int p = 1; p < PARTS; ++p) {
        const u64* pl = &g_part[base + (size_t)p * NS];
#pragma unroll 1
        for (int s = 0; s < NS; ++s) {
            u64 cand = pl[s];
            if (cand >= e[NS - 1]) break;   // part lists are sorted ascending
            insert21(e, cand);
        }
    }

    // e[0] is the self/nearest (dropped, mirrors idx[:,:,1:]); order of the
    // remaining 20 is irrelevant downstream (sum / max over k).
    int ob = i * Kc;
#pragma unroll
    for (int s = 1; s < NS; ++s)
        g_idx[ob + s - 1] = (int)(e[s] & 0xFFFFFFFFu);
}

// ---------------- kernel 3: P,Q = small GEMMs -----------------------------
// P[b][n][o] = sum_c (W[o][c]-W[o][64+c]) x[b][c][n] + bias[o]
// Q[b][n][o] = sum_c  W[o][64+c]          x[b][c][n]
__global__ __launch_bounds__(256) void k_pq(const float* __restrict__ x,
                                            const float* __restrict__ W,
                                            const float* __restrict__ bias) {
    __shared__ float Wp[Cc][64];
    __shared__ float Wq[Cc][64];
    const int tid = threadIdx.x;
    for (int i = tid; i < 64 * Cc; i += 256) {
        int o = i >> 6, c = i & 63;
        float w1 = W[o * 2 * Cc + c];
        float w2 = W[o * 2 * Cc + Cc + c];
        Wp[c][o] = w1 - w2;
        Wq[c][o] = w2;
    }
    __syncthreads();

    const int o  = tid & 63, nl = tid >> 6;
    const int b  = blockIdx.y;
    const int n0 = blockIdx.x * 64;
    const float bv = bias[o];

    for (int ni = 0; ni < 8; ++ni) {
        int n = n0 + ni * 8 + nl;            // + twin column n+4
        const float* xp = x + (size_t)b * Cc * Nc + n;
        float p0 = 0.f, q0 = 0.f, p1 = 0.f, q1 = 0.f;
#pragma unroll
        for (int c = 0; c < Cc; ++c) {
            float xv0 = __ldg(&xp[(size_t)c * Nc]);
            float xv1 = __ldg(&xp[(size_t)c * Nc + 4]);
            float wp = Wp[c][o], wq = Wq[c][o];
            p0 = fmaf(wp, xv0, p0);
            q0 = fmaf(wq, xv0, q0);
            p1 = fmaf(wp, xv1, p1);
            q1 = fmaf(wq, xv1, q1);
        }
        size_t r0 = ((size_t)(b * Nc + n)) * 64 + o;
        g_P[r0] = p0 + bv;          g_Q[r0] = q0;
        g_P[r0 + 4 * 64] = p1 + bv; g_Q[r0 + 4 * 64] = q1;
    }
}

// ---------------- kernel 4: BN statistics pass ----------------------------
__global__ __launch_bounds__(256) void k_stats() {
    const int tid = threadIdx.x;
    const int o = tid & 63, nl = tid >> 6;
    const int b = blockIdx.y;
    const int n0 = blockIdx.x * 32;

    float s = 0.f, ss = 0.f;
    for (int ni = 0; ni < 8; ++ni) {
        int n = n0 + ni * 4 + nl;
        int row = b * Nc + n;
        float pv = g_P[(size_t)row * 64 + o];
        const int* ip = &g_idx[row * Kc];
#pragma unroll
        for (int k = 0; k < Kc; ++k) {
            int m = ip[k];
            float qv = g_Q[((size_t)(b * Nc + m)) * 64 + o];
            float y = pv + qv;
            s += y;
            ss = fmaf(y, y, ss);
        }
    }
    __shared__ float rs[4][64], rss[4][64];
    rs[nl][o] = s; rss[nl][o] = ss;
    __syncthreads();
    if (nl == 0) {
        float st  = rs[0][o] + rs[1][o] + rs[2][o] + rs[3][o];
        float sst = rss[0][o] + rss[1][o] + rss[2][o] + rss[3][o];
        atomicAdd(&g_sum[o],   (double)st);
        atomicAdd(&g_sumsq[o], (double)sst);
    }
}

// ---------------- kernel 5: finalize BN coefficients ----------------------
__global__ void k_finalize(const float* __restrict__ gamma,
                           const float* __restrict__ beta) {
    int o = threadIdx.x;
    if (o < 64) {
        const double cnt = (double)Bc * Nc * Kc;
        double mean = g_sum[o] / cnt;
        double var  = g_sumsq[o] / cnt - mean * mean;
        float sc = gamma[o] * (float)(1.0 / sqrt(var + 1e-5));
        g_scale[o] = sc;
        g_shift[o] = beta[o] - (float)mean * sc;
    }
}

// ---------------- kernel 6: normalize + relu + max over k -----------------
__global__ __launch_bounds__(256) void k_out(float* __restrict__ out) {
    __shared__ float tile[64][33];   // +1 pad: conflict-free transpose
    const int tid = threadIdx.x;
    const int o = tid & 63, nl = tid >> 6;
    const int b = blockIdx.y;
    const int n0 = blockIdx.x * 32;
    const float sc = g_scale[o], sh = g_shift[o];

    for (int ni = 0; ni < 8; ++ni) {
        int n = n0 + ni * 4 + nl;
        int row = b * Nc + n;
        float pv = g_P[(size_t)row * 64 + o];
        const int* ip = &g_idx[row * Kc];
        float best = -3.4e38f;
#pragma unroll
        for (int k = 0; k < Kc; ++k) {
            int m = ip[k];
            float qv = g_Q[((size_t)(b * Nc + m)) * 64 + o];
            float v = fmaf(pv + qv, sc, sh);
            best = fmaxf(best, v);
        }
        // max_k relu(v) == relu(max_k v)
        tile[o][ni * 4 + nl] = fmaxf(best, 0.f);
    }
    __syncthreads();

    // coalesced store: out layout (B, O, N)
    const int lane = tid & 31, w = tid >> 5;   // 8 warps
    for (int o2 = w; o2 < 64; o2 += 8) {
        out[((size_t)(b * 64 + o2)) * Nc + n0 + lane] = tile[o2][lane];
    }
}

// ---------------- launcher -------------------------------------------------
extern "C" void kernel_launch(void* const* d_in, const int* in_sizes, int n_in,
                              void* d_out, int out_size) {
    const float* x     = (const float*)d_in[0];   // (B, C, N)
    const float* W     = (const float*)d_in[1];   // (O, 2C)
    const float* bias  = (const float*)d_in[2];   // (O,)
    const float* gamma = (const float*)d_in[3];   // (O,)
    const float* beta  = (const float*)d_in[4];   // (O,)
    float* out = (float*)d_out;                   // (B, O, N)

    k_zero<<<1, 64>>>();
    k_sqnorm<<<(Bc * Nc + 255) / 256, 256>>>(x);
    k_knn_part<<<dim3(Nc / 128, PARTS, Bc), 128>>>(x);
    k_merge<<<(Bc * Nc + 255) / 256, 256>>>();
    k_pq<<<dim3(Nc / 64, Bc), 256>>>(x, W, bias);
    k_stats<<<dim3(Nc / 32, Bc), 256>>>();
    k_finalize<<<1, 64>>>(gamma, beta);
    k_out<<<dim3(Nc / 32, Bc), 256>>>(out);
}

// round 13
// speedup vs baseline: 1.1716x; 1.1709x over previous
#include <cuda_runtime.h>
#include <cstdint>

#define Bc 8
#define Cc 64
#define Nc 4096
#define Kc 20
#define NS 21   // keep top-21 (self + 20), self dropped at the end

typedef unsigned long long u64;

// ---------------- device scratch (no allocations allowed) ----------------
__device__ float  g_sq[Bc * Nc];                 // squared norms per point
__device__ int    g_idx[Bc * Nc * Kc];           // knn indices (within batch)
__device__ float  g_P[Bc * Nc * 64];             // (W1-W2)·x_n + b   [b][n][o]
__device__ float  g_Q[Bc * Nc * 64];             // W2·x_m            [b][m][o]
__device__ double g_sum[64];
__device__ double g_sumsq[64];
__device__ float  g_scale[64];
__device__ float  g_shift[64];

// ---------------- kernel 0: zero BN accumulators (graph-replay safe) -----
__global__ void k_zero() {
    int o = threadIdx.x;
    if (o < 64) { g_sum[o] = 0.0; g_sumsq[o] = 0.0; }
}

// ---------------- kernel 1: squared norms --------------------------------
__global__ void k_sqnorm(const float* __restrict__ x) {
    int i = blockIdx.x * blockDim.x + threadIdx.x;   // i = b*N + n
    if (i >= Bc * Nc) return;
    int b = i / Nc, n = i % Nc;
    const float* xb = x + (size_t)b * Cc * Nc + n;
    float s = 0.f;
#pragma unroll
    for (int c = 0; c < Cc; ++c) {
        float v = xb[(size_t)c * Nc];
        s = fmaf(v, v, s);
    }
    g_sq[i] = s;
}

// ---------------- kNN helpers --------------------------------------------
// Monotone map float -> u32 so integer compare == (float, then idx) lexicographic.
__device__ __forceinline__ u64 make_key(float d, int m) {
    int bb = __float_as_int(d);
    unsigned ub = (unsigned)bb ^ ((unsigned)(bb >> 31) | 0x80000000u);
    return ((u64)ub << 32) | (unsigned)m;
}

// Branchless shift-insert into sorted-ascending e[0..20].
// Precondition: cand < e[20].
__device__ __forceinline__ void insert21(u64 (&e)[NS], u64 cand) {
    bool ltc = true;              // cand < conceptual e[21]
#pragma unroll
    for (int s = NS - 1; s >= 1; --s) {
        bool ltp = cand < e[s - 1];
        e[s] = ltp ? e[s - 1] : (ltc ? cand : e[s]);
        ltc = ltp;
    }
    e[0] = ltc ? cand : e[0];
}

#define FMA2(acc, a, b) asm("fma.rn.f32x2 %0, %1, %2, %0;" : "+l"(acc) : "l"(a), "l"(b))

// Drain this lane's queue into its register top-21.  One insert21 execution
// serves up to 32 lanes in parallel (the whole point of the queue).
// Must be called with the full warp converged.
__device__ __forceinline__ void drain_queue(u64 (&e)[NS],
                                            volatile u64* qb,  // qbuf base, [slot][128]
                                            int t, unsigned& cnt, u64& thr) {
    for (int j = 0; j < 16; ++j) {
        bool act = (j < (int)cnt);
        if (!__any_sync(0xFFFFFFFFu, act)) break;
        if (act) {
            u64 cand = qb[j * 128 + t];
            if (cand < e[NS - 1]) insert21(e, cand);   // re-check vs fresh threshold
        }
    }
    cnt = 0;
    thr = e[NS - 1];
}

// ---------------- kernel 2: kNN (thread per query) ------------------------
// 128 queries / block; query vector in registers; candidate tiles of 32 in
// SMEM; 16-candidate-wide packed f32x2 dot; per-lane SMEM queues batch the
// top-k insertions so the warp pays one shift-insert per ~8 passing keys.
__global__ __launch_bounds__(128, 2) void k_knn(const float* __restrict__ x) {
    __shared__ float cs[Cc][32];
    __shared__ float csq[32];
    __shared__ u64   qbuf[16][128];    // [slot][tid] : 2-phase conflict-free

    const int t  = threadIdx.x;
    const int b  = blockIdx.y;
    const int n0 = blockIdx.x * 128;
    const float* xb = x + (size_t)b * Cc * Nc;

    // query into registers
    float q[Cc];
#pragma unroll
    for (int c = 0; c < Cc; ++c)
        q[c] = xb[(size_t)c * Nc + n0 + t];
    const float sqq = g_sq[b * Nc + n0 + t];

    // sorted top-21 keys, ascending; sentinel inits above any real key
    u64 e[NS];
#pragma unroll
    for (int s = 0; s < NS; ++s) e[s] = 0xFFFFFFFF00000000ull + (unsigned)s;

    unsigned cnt = 0;          // per-lane queue occupancy
    u64 thr = e[NS - 1];       // cached (possibly stale) threshold

    for (int m0 = 0; m0 < Nc; m0 += 32) {
        __syncthreads();
        // cooperative coalesced load of 32x64 candidate tile
        for (int idx = t; idx < 32 * Cc; idx += 128) {
            int c = idx >> 5, m = idx & 31;
            cs[c][m] = xb[(size_t)c * Nc + m0 + m];
        }
        if (t < 32) csq[t] = g_sq[b * Nc + m0 + t];
        __syncthreads();

#pragma unroll 1
        for (int half = 0; half < 32; half += 16) {
            u64 acc[8];
#pragma unroll
            for (int i = 0; i < 8; ++i) acc[i] = 0ull;

#pragma unroll
            for (int c = 0; c < Cc; ++c) {
                u64 qq;
                asm("mov.b64 %0, {%1, %1};" : "=l"(qq) : "f"(q[c]));
                const ulonglong2* p = reinterpret_cast<const ulonglong2*>(&cs[c][half]);
                ulonglong2 v0 = p[0];
                ulonglong2 v1 = p[1];
                ulonglong2 v2 = p[2];
                ulonglong2 v3 = p[3];
                FMA2(acc[0], qq, v0.x); FMA2(acc[1], qq, v0.y);
                FMA2(acc[2], qq, v1.x); FMA2(acc[3], qq, v1.y);
                FMA2(acc[4], qq, v2.x); FMA2(acc[5], qq, v2.y);
                FMA2(acc[6], qq, v3.x); FMA2(acc[7], qq, v3.y);
            }

            // two 8-candidate chunks: keys, queue-append, drain check
#pragma unroll
            for (int sub = 0; sub < 2; ++sub) {
                float d[8];
                asm("mov.b64 {%0, %1}, %2;" : "=f"(d[0]), "=f"(d[1]) : "l"(acc[sub*4 + 0]));
                asm("mov.b64 {%0, %1}, %2;" : "=f"(d[2]), "=f"(d[3]) : "l"(acc[sub*4 + 1]));
                asm("mov.b64 {%0, %1}, %2;" : "=f"(d[4]), "=f"(d[5]) : "l"(acc[sub*4 + 2]));
                asm("mov.b64 {%0, %1}, %2;" : "=f"(d[6]), "=f"(d[7]) : "l"(acc[sub*4 + 3]));

#pragma unroll
                for (int i = 0; i < 8; ++i) {
                    int jl = half + sub * 8 + i;           // index within tile
                    float dd = sqq + csq[jl] - 2.f * d[i];
                    u64 key = make_key(dd, m0 + jl);
                    if (key < thr) {                       // cheap per-lane gate
                        qbuf[cnt][t] = key;                // STS.64, own column
                        ++cnt;
                    }
                }
                // capacity 16, appends per chunk <= 8, so drain at cnt >= 8
                if (__any_sync(0xFFFFFFFFu, cnt >= 8))
                    drain_queue(e, &qbuf[0][0], t, cnt, thr);
            }
        }
    }

    // flush remaining queued keys
    drain_queue(e, &qbuf[0][0], t, cnt, thr);

    // e[0] is the self/nearest (dropped, mirrors idx[:,:,1:]); order of the
    // remaining 20 is irrelevant downstream (sum / max over k).
    int base = (b * Nc + n0 + t) * Kc;
#pragma unroll
    for (int s = 1; s < NS; ++s)
        g_idx[base + s - 1] = (int)(e[s] & 0xFFFFFFFFu);
}

// ---------------- kernel 3: P,Q = small GEMMs -----------------------------
// P[b][n][o] = sum_c (W[o][c]-W[o][64+c]) x[b][c][n] + bias[o]
// Q[b][n][o] = sum_c  W[o][64+c]          x[b][c][n]
__global__ __launch_bounds__(256) void k_pq(const float* __restrict__ x,
                                            const float* __restrict__ W,
                                            const float* __restrict__ bias) {
    __shared__ float Wp[Cc][64];
    __shared__ float Wq[Cc][64];
    const int tid = threadIdx.x;
    for (int i = tid; i < 64 * Cc; i += 256) {
        int o = i >> 6, c = i & 63;
        float w1 = W[o * 2 * Cc + c];
        float w2 = W[o * 2 * Cc + Cc + c];
        Wp[c][o] = w1 - w2;
        Wq[c][o] = w2;
    }
    __syncthreads();

    const int o  = tid & 63, nl = tid >> 6;
    const int b  = blockIdx.y;
    const int n0 = blockIdx.x * 64;
    const float bv = bias[o];

    for (int ni = 0; ni < 8; ++ni) {
        int n = n0 + ni * 8 + nl;            // + twin column n+4
        const float* xp = x + (size_t)b * Cc * Nc + n;
        float p0 = 0.f, q0 = 0.f, p1 = 0.f, q1 = 0.f;
#pragma unroll
        for (int c = 0; c < Cc; ++c) {
            float xv0 = __ldg(&xp[(size_t)c * Nc]);
            float xv1 = __ldg(&xp[(size_t)c * Nc + 4]);
            float wp = Wp[c][o], wq = Wq[c][o];
            p0 = fmaf(wp, xv0, p0);
            q0 = fmaf(wq, xv0, q0);
            p1 = fmaf(wp, xv1, p1);
            q1 = fmaf(wq, xv1, q1);
        }
        size_t r0 = ((size_t)(b * Nc + n)) * 64 + o;
        g_P[r0] = p0 + bv;          g_Q[r0] = q0;
        g_P[r0 + 4 * 64] = p1 + bv; g_Q[r0 + 4 * 64] = q1;
    }
}

// ---------------- kernel 4: BN statistics pass ----------------------------
__global__ __launch_bounds__(256) void k_stats() {
    const int tid = threadIdx.x;
    const int o = tid & 63, nl = tid >> 6;
    const int b = blockIdx.y;
    const int n0 = blockIdx.x * 32;

    float s = 0.f, ss = 0.f;
    for (int ni = 0; ni < 8; ++ni) {
        int n = n0 + ni * 4 + nl;
        int row = b * Nc + n;
        float pv = g_P[(size_t)row * 64 + o];
        const int* ip = &g_idx[row * Kc];
#pragma unroll
        for (int k = 0; k < Kc; ++k) {
            int m = ip[k];
            float qv = g_Q[((size_t)(b * Nc + m)) * 64 + o];
            float y = pv + qv;
            s += y;
            ss = fmaf(y, y, ss);
        }
    }
    __shared__ float rs[4][64], rss[4][64];
    rs[nl][o] = s; rss[nl][o] = ss;
    __syncthreads();
    if (nl == 0) {
        float st  = rs[0][o] + rs[1][o] + rs[2][o] + rs[3][o];
        float sst = rss[0][o] + rss[1][o] + rss[2][o] + rss[3][o];
        atomicAdd(&g_sum[o],   (double)st);
        atomicAdd(&g_sumsq[o], (double)sst);
    }
}

// ---------------- kernel 5: finalize BN coefficients ----------------------
__global__ void k_finalize(const float* __restrict__ gamma,
                           const float* __restrict__ beta) {
    int o = threadIdx.x;
    if (o < 64) {
        const double cnt = (double)Bc * Nc * Kc;
        double mean = g_sum[o] / cnt;
        double var  = g_sumsq[o] / cnt - mean * mean;
        float sc = gamma[o] * (float)(1.0 / sqrt(var + 1e-5));
        g_scale[o] = sc;
        g_shift[o] = beta[o] - (float)mean * sc;
    }
}

// ---------------- kernel 6: normalize + relu + max over k -----------------
__global__ __launch_bounds__(256) void k_out(float* __restrict__ out) {
    __shared__ float tile[64][33];   // +1 pad: conflict-free transpose
    const int tid = threadIdx.x;
    const int o = tid & 63, nl = tid >> 6;
    const int b = blockIdx.y;
    const int n0 = blockIdx.x * 32;
    const float sc = g_scale[o], sh = g_shift[o];

    for (int ni = 0; ni < 8; ++ni) {
        int n = n0 + ni * 4 + nl;
        int row = b * Nc + n;
        float pv = g_P[(size_t)row * 64 + o];
        const int* ip = &g_idx[row * Kc];
        float best = -3.4e38f;
#pragma unroll
        for (int k = 0; k < Kc; ++k) {
            int m = ip[k];
            float qv = g_Q[((size_t)(b * Nc + m)) * 64 + o];
            float v = fmaf(pv + qv, sc, sh);
            best = fmaxf(best, v);
        }
        // max_k relu(v) == relu(max_k v)
        tile[o][ni * 4 + nl] = fmaxf(best, 0.f);
    }
    __syncthreads();

    // coalesced store: out layout (B, O, N)
    const int lane = tid & 31, w = tid >> 5;   // 8 warps
    for (int o2 = w; o2 < 64; o2 += 8) {
        out[((size_t)(b * 64 + o2)) * Nc + n0 + lane] = tile[o2][lane];
    }
}

// ---------------- launcher -------------------------------------------------
extern "C" void kernel_launch(void* const* d_in, const int* in_sizes, int n_in,
                              void* d_out, int out_size) {
    const float* x     = (const float*)d_in[0];   // (B, C, N)
    const float* W     = (const float*)d_in[1];   // (O, 2C)
    const float* bias  = (const float*)d_in[2];   // (O,)
    const float* gamma = (const float*)d_in[3];   // (O,)
    const float* beta  = (const float*)d_in[4];   // (O,)
    float* out = (float*)d_out;                   // (B, O, N)

    k_zero<<<1, 64>>>();
    k_sqnorm<<<(Bc * Nc + 255) / 256, 256>>>(x);
    k_pq<<<dim3(Nc / 64, Bc), 256>>>(x, W, bias);     // moved: knn now launch #3 (profiled)
    k_knn<<<dim3(Nc / 128, Bc), 128>>>(x);
    k_stats<<<dim3(Nc / 32, Bc), 256>>>();
    k_finalize<<<1, 64>>>(gamma, beta);
    k_out<<<dim3(Nc / 32, Bc), 256>>>(out);
}

// round 14
// speedup vs baseline: 1.3434x; 1.1466x over previous
#include <cuda_runtime.h>
#include <cstdint>

#define Bc 8
#define Cc 64
#define Nc 4096
#define Kc 20
#define NS 21        // top-21 (self + 20), self dropped after merge
#define PARTS 2
#define PLEN (Nc / PARTS)
#define QCAP 16

typedef unsigned long long u64;

// ---------------- device scratch (no allocations allowed) ----------------
__device__ float  g_sq[Bc * Nc];                  // squared norms per point
__device__ u64    g_part[Bc * Nc * PARTS * NS];   // per-part sorted top-21 keys
__device__ int    g_idx[Bc * Nc * Kc];            // knn indices (within batch)
__device__ float  g_P[Bc * Nc * 64];              // (W1-W2)·x_n + b   [b][n][o]
__device__ float  g_Q[Bc * Nc * 64];              // W2·x_m            [b][m][o]
__device__ double g_sum[64];
__device__ double g_sumsq[64];
__device__ float  g_scale[64];
__device__ float  g_shift[64];

// ---------------- kernel 0: zero BN accumulators (graph-replay safe) -----
__global__ void k_zero() {
    int o = threadIdx.x;
    if (o < 64) { g_sum[o] = 0.0; g_sumsq[o] = 0.0; }
}

// ---------------- kernel 1: squared norms --------------------------------
__global__ void k_sqnorm(const float* __restrict__ x) {
    int i = blockIdx.x * blockDim.x + threadIdx.x;   // i = b*N + n
    if (i >= Bc * Nc) return;
    int b = i / Nc, n = i % Nc;
    const float* xb = x + (size_t)b * Cc * Nc + n;
    float s = 0.f;
#pragma unroll
    for (int c = 0; c < Cc; ++c) {
        float v = xb[(size_t)c * Nc];
        s = fmaf(v, v, s);
    }
    g_sq[i] = s;
}

// ---------------- kNN helpers --------------------------------------------
// Monotone map float -> u32 so integer compare == (float, then idx) lexicographic.
__device__ __forceinline__ u64 make_key(float d, int m) {
    int bb = __float_as_int(d);
    unsigned ub = (unsigned)bb ^ ((unsigned)(bb >> 31) | 0x80000000u);
    return ((u64)ub << 32) | (unsigned)m;
}

// Branchless shift-insert into sorted-ascending e[0..20].
// Precondition: cand < e[20].
__device__ __forceinline__ void insert21(u64 (&e)[NS], u64 cand) {
    bool ltc = true;              // cand < conceptual e[21]
#pragma unroll
    for (int s = NS - 1; s >= 1; --s) {
        bool ltp = cand < e[s - 1];
        e[s] = ltp ? e[s - 1] : (ltc ? cand : e[s]);
        ltc = ltp;
    }
    e[0] = ltc ? cand : e[0];
}

#define FMA2(acc, a, b) asm("fma.rn.f32x2 %0, %1, %2, %0;" : "+l"(acc) : "l"(a), "l"(b))
#define SPLAT(qq, f)    asm("mov.b64 %0, {%1, %1};" : "=l"(qq) : "f"(f))

// Drain one lane-column queue into the register top-21.  One insert21
// execution serves up to 32 lanes.  Call warp-converged.
__device__ __forceinline__ void drain_queue(u64 (&e)[NS],
                                            volatile u64* qb,  // [slot][64]
                                            int t, unsigned& cnt, u64& thr) {
    for (int j = 0; j < QCAP; ++j) {
        bool act = (j < (int)cnt);
        if (!__any_sync(0xFFFFFFFFu, act)) break;
        if (act) {
            u64 cand = qb[j * 64 + t];
            if (cand < e[NS - 1]) insert21(e, cand);   // re-check fresh threshold
        }
    }
    cnt = 0;
    thr = e[NS - 1];
}

// ---------------- kernel 2: partial kNN, 2 queries per thread -------------
// 64 threads / block; thread owns queries n0+t and n0+64+t (both vectors in
// registers).  Candidate tiles of 32 in SMEM; each LDS.128 feeds FMA2 chains
// of BOTH queries (halves L1 wavefronts).  Per-lane SMEM queues batch the
// top-k insertions.  Each block scans one of PARTS candidate halves.
__global__ __launch_bounds__(64, 4) void k_knn_part(const float* __restrict__ x) {
    __shared__ float cs[Cc][32];
    __shared__ float csq[32];
    __shared__ u64   qb0[QCAP][64];
    __shared__ u64   qb1[QCAP][64];

    const int t    = threadIdx.x;
    const int part = blockIdx.y;
    const int b    = blockIdx.z;
    const int n0   = blockIdx.x * 128;
    const float* xb = x + (size_t)b * Cc * Nc;

    float q0[Cc], q1[Cc];
#pragma unroll
    for (int c = 0; c < Cc; ++c) {
        q0[c] = xb[(size_t)c * Nc + n0 + t];
        q1[c] = xb[(size_t)c * Nc + n0 + 64 + t];
    }
    const float sq0 = g_sq[b * Nc + n0 + t];
    const float sq1 = g_sq[b * Nc + n0 + 64 + t];

    u64 e0[NS], e1[NS];
#pragma unroll
    for (int s = 0; s < NS; ++s) {
        e0[s] = 0xFFFFFFFF00000000ull + (unsigned)s;
        e1[s] = 0xFFFFFFFF00000000ull + (unsigned)s;
    }
    unsigned cnt0 = 0, cnt1 = 0;
    u64 thr0 = e0[NS - 1], thr1 = e1[NS - 1];

    const int mbase = part * PLEN;
    for (int m0 = mbase; m0 < mbase + PLEN; m0 += 32) {
        __syncthreads();
        for (int idx = t; idx < 32 * Cc; idx += 64) {
            int c = idx >> 5, m = idx & 31;
            cs[c][m] = xb[(size_t)c * Nc + m0 + m];
        }
        if (t < 32) csq[t] = g_sq[b * Nc + m0 + t];
        __syncthreads();

#pragma unroll 1
        for (int j = 0; j < 32; j += 8) {
            u64 a00 = 0, a01 = 0, a02 = 0, a03 = 0;
            u64 a10 = 0, a11 = 0, a12 = 0, a13 = 0;
#pragma unroll
            for (int c = 0; c < Cc; ++c) {
                u64 qq0, qq1;
                SPLAT(qq0, q0[c]);
                SPLAT(qq1, q1[c]);
                ulonglong2 p0 = *reinterpret_cast<const ulonglong2*>(&cs[c][j]);
                ulonglong2 p1 = *reinterpret_cast<const ulonglong2*>(&cs[c][j + 4]);
                FMA2(a00, qq0, p0.x); FMA2(a01, qq0, p0.y);
                FMA2(a02, qq0, p1.x); FMA2(a03, qq0, p1.y);
                FMA2(a10, qq1, p0.x); FMA2(a11, qq1, p0.y);
                FMA2(a12, qq1, p1.x); FMA2(a13, qq1, p1.y);
            }
            float d0[8], d1[8];
            asm("mov.b64 {%0, %1}, %2;" : "=f"(d0[0]), "=f"(d0[1]) : "l"(a00));
            asm("mov.b64 {%0, %1}, %2;" : "=f"(d0[2]), "=f"(d0[3]) : "l"(a01));
            asm("mov.b64 {%0, %1}, %2;" : "=f"(d0[4]), "=f"(d0[5]) : "l"(a02));
            asm("mov.b64 {%0, %1}, %2;" : "=f"(d0[6]), "=f"(d0[7]) : "l"(a03));
            asm("mov.b64 {%0, %1}, %2;" : "=f"(d1[0]), "=f"(d1[1]) : "l"(a10));
            asm("mov.b64 {%0, %1}, %2;" : "=f"(d1[2]), "=f"(d1[3]) : "l"(a11));
            asm("mov.b64 {%0, %1}, %2;" : "=f"(d1[4]), "=f"(d1[5]) : "l"(a12));
            asm("mov.b64 {%0, %1}, %2;" : "=f"(d1[6]), "=f"(d1[7]) : "l"(a13));

#pragma unroll
            for (int i = 0; i < 8; ++i) {
                float c2 = csq[j + i];
                int   mi = m0 + j + i;
                float dd0 = sq0 + c2 - 2.f * d0[i];
                float dd1 = sq1 + c2 - 2.f * d1[i];
                u64 k0 = make_key(dd0, mi);
                u64 k1 = make_key(dd1, mi);
                if (k0 < thr0) { qb0[cnt0][t] = k0; ++cnt0; }
                if (k1 < thr1) { qb1[cnt1][t] = k1; ++cnt1; }
            }
            if (__any_sync(0xFFFFFFFFu, cnt0 >= 9))
                drain_queue(e0, &qb0[0][0], t, cnt0, thr0);
            if (__any_sync(0xFFFFFFFFu, cnt1 >= 9))
                drain_queue(e1, &qb1[0][0], t, cnt1, thr1);
        }
    }

    drain_queue(e0, &qb0[0][0], t, cnt0, thr0);
    drain_queue(e1, &qb1[0][0], t, cnt1, thr1);

    // write sorted part lists (ascending)
    size_t base0 = ((size_t)(b * Nc + n0 + t)      * PARTS + part) * NS;
    size_t base1 = ((size_t)(b * Nc + n0 + 64 + t) * PARTS + part) * NS;
#pragma unroll
    for (int s = 0; s < NS; ++s) {
        g_part[base0 + s] = e0[s];
        g_part[base1 + s] = e1[s];
    }
}

// ---------------- kernel 2b: merge part lists -----------------------------
__global__ __launch_bounds__(256) void k_merge() {
    int i = blockIdx.x * 256 + threadIdx.x;   // query id = b*N + n
    if (i >= Bc * Nc) return;
    size_t base = (size_t)i * PARTS * NS;

    u64 e[NS];
#pragma unroll
    for (int s = 0; s < NS; ++s) e[s] = g_part[base + s];

    for (int p = 1; p < PARTS; ++p) {
        const u64* pl = &g_part[base + (size_t)p * NS];
#pragma unroll 1
        for (int s = 0; s < NS; ++s) {
            u64 cand = pl[s];
            if (cand >= e[NS - 1]) break;   // part lists are sorted ascending
            insert21(e, cand);
        }
    }

    // e[0] is the self/nearest (dropped, mirrors idx[:,:,1:]); order of the
    // remaining 20 is irrelevant downstream (sum / max over k).
    int ob = i * Kc;
#pragma unroll
    for (int s = 1; s < NS; ++s)
        g_idx[ob + s - 1] = (int)(e[s] & 0xFFFFFFFFu);
}

// ---------------- kernel 3: P,Q = small GEMMs -----------------------------
// P[b][n][o] = sum_c (W[o][c]-W[o][64+c]) x[b][c][n] + bias[o]
// Q[b][n][o] = sum_c  W[o][64+c]          x[b][c][n]
__global__ __launch_bounds__(256) void k_pq(const float* __restrict__ x,
                                            const float* __restrict__ W,
                                            const float* __restrict__ bias) {
    __shared__ float Wp[Cc][64];
    __shared__ float Wq[Cc][64];
    const int tid = threadIdx.x;
    for (int i = tid; i < 64 * Cc; i += 256) {
        int o = i >> 6, c = i & 63;
        float w1 = W[o * 2 * Cc + c];
        float w2 = W[o * 2 * Cc + Cc + c];
        Wp[c][o] = w1 - w2;
        Wq[c][o] = w2;
    }
    __syncthreads();

    const int o  = tid & 63, nl = tid >> 6;
    const int b  = blockIdx.y;
    const int n0 = blockIdx.x * 64;
    const float bv = bias[o];

    for (int ni = 0; ni < 8; ++ni) {
        int n = n0 + ni * 8 + nl;            // + twin column n+4
        const float* xp = x + (size_t)b * Cc * Nc + n;
        float p0 = 0.f, q0 = 0.f, p1 = 0.f, q1 = 0.f;
#pragma unroll
        for (int c = 0; c < Cc; ++c) {
            float xv0 = __ldg(&xp[(size_t)c * Nc]);
            float xv1 = __ldg(&xp[(size_t)c * Nc + 4]);
            float wp = Wp[c][o], wq = Wq[c][o];
            p0 = fmaf(wp, xv0, p0);
            q0 = fmaf(wq, xv0, q0);
            p1 = fmaf(wp, xv1, p1);
            q1 = fmaf(wq, xv1, q1);
        }
        size_t r0 = ((size_t)(b * Nc + n)) * 64 + o;
        g_P[r0] = p0 + bv;          g_Q[r0] = q0;
        g_P[r0 + 4 * 64] = p1 + bv; g_Q[r0 + 4 * 64] = q1;
    }
}

// ---------------- kernel 4: BN statistics pass ----------------------------
__global__ __launch_bounds__(256) void k_stats() {
    const int tid = threadIdx.x;
    const int o = tid & 63, nl = tid >> 6;
    const int b = blockIdx.y;
    const int n0 = blockIdx.x * 32;

    float s = 0.f, ss = 0.f;
    for (int ni = 0; ni < 8; ++ni) {
        int n = n0 + ni * 4 + nl;
        int row = b * Nc + n;
        float pv = g_P[(size_t)row * 64 + o];
        const int* ip = &g_idx[row * Kc];
#pragma unroll
        for (int k = 0; k < Kc; ++k) {
            int m = ip[k];
            float qv = g_Q[((size_t)(b * Nc + m)) * 64 + o];
            float y = pv + qv;
            s += y;
            ss = fmaf(y, y, ss);
        }
    }
    __shared__ float rs[4][64], rss[4][64];
    rs[nl][o] = s; rss[nl][o] = ss;
    __syncthreads();
    if (nl == 0) {
        float st  = rs[0][o] + rs[1][o] + rs[2][o] + rs[3][o];
        float sst = rss[0][o] + rss[1][o] + rss[2][o] + rss[3][o];
        atomicAdd(&g_sum[o],   (double)st);
        atomicAdd(&g_sumsq[o], (double)sst);
    }
}

// ---------------- kernel 5: finalize BN coefficients ----------------------
__global__ void k_finalize(const float* __restrict__ gamma,
                           const float* __restrict__ beta) {
    int o = threadIdx.x;
    if (o < 64) {
        const double cnt = (double)Bc * Nc * Kc;
        double mean = g_sum[o] / cnt;
        double var  = g_sumsq[o] / cnt - mean * mean;
        float sc = gamma[o] * (float)(1.0 / sqrt(var + 1e-5));
        g_scale[o] = sc;
        g_shift[o] = beta[o] - (float)mean * sc;
    }
}

// ---------------- kernel 6: normalize + relu + max over k -----------------
__global__ __launch_bounds__(256) void k_out(float* __restrict__ out) {
    __shared__ float tile[64][33];   // +1 pad: conflict-free transpose
    const int tid = threadIdx.x;
    const int o = tid & 63, nl = tid >> 6;
    const int b = blockIdx.y;
    const int n0 = blockIdx.x * 32;
    const float sc = g_scale[o], sh = g_shift[o];

    for (int ni = 0; ni < 8; ++ni) {
        int n = n0 + ni * 4 + nl;
        int row = b * Nc + n;
        float pv = g_P[(size_t)row * 64 + o];
        const int* ip = &g_idx[row * Kc];
        float best = -3.4e38f;
#pragma unroll
        for (int k = 0; k < Kc; ++k) {
            int m = ip[k];
            float qv = g_Q[((size_t)(b * Nc + m)) * 64 + o];
            float v = fmaf(pv + qv, sc, sh);
            best = fmaxf(best, v);
        }
        // max_k relu(v) == relu(max_k v)
        tile[o][ni * 4 + nl] = fmaxf(best, 0.f);
    }
    __syncthreads();

    // coalesced store: out layout (B, O, N)
    const int lane = tid & 31, w = tid >> 5;   // 8 warps
    for (int o2 = w; o2 < 64; o2 += 8) {
        out[((size_t)(b * 64 + o2)) * Nc + n0 + lane] = tile[o2][lane];
    }
}

// ---------------- launcher -------------------------------------------------
extern "C" void kernel_launch(void* const* d_in, const int* in_sizes, int n_in,
                              void* d_out, int out_size) {
    const float* x     = (const float*)d_in[0];   // (B, C, N)
    const float* W     = (const float*)d_in[1];   // (O, 2C)
    const float* bias  = (const float*)d_in[2];   // (O,)
    const float* gamma = (const float*)d_in[3];   // (O,)
    const float* beta  = (const float*)d_in[4];   // (O,)
    float* out = (float*)d_out;                   // (B, O, N)

    k_zero<<<1, 64>>>();
    k_sqnorm<<<(Bc * Nc + 255) / 256, 256>>>(x);
    k_pq<<<dim3(Nc / 64, Bc), 256>>>(x, W, bias);
    k_knn_part<<<dim3(Nc / 128, PARTS, Bc), 64>>>(x);
    k_merge<<<(Bc * Nc + 255) / 256, 256>>>();
    k_stats<<<dim3(Nc / 32, Bc), 256>>>();
    k_finalize<<<1, 64>>>(gamma, beta);
    k_out<<<dim3(Nc / 32, Bc), 256>>>(out);
}